// round 1
// baseline (speedup 1.0000x reference)
#include <cuda_runtime.h>

// Critic_66511863546286 — algebraically folded attention critic.
// B=256, S=1024, H=256, static/dynamic feature dims = 2, 3 process iterations.
//
// Key identity: every column of `energy` is affine in 6 scalars
// (x0,x1,y0,y1,z0,z1), and ctx = sw·xbar + sb because softmax sums to 1.
// So W @ energy collapses from [H,3H]x[3H] per (b,s) to 6 FMAs per (b,s,h).

#define NB 256
#define NS 1024
#define NH 256
#define K3 768
#define NITER 3
#define NFC 20

// Precomputed, pre-scaled (by 2*log2(e)) fused coefficients.
__device__ float4 gAB[NH];   // (A0, A1, B0, B1) * 2log2e
__device__ float4 gCd[NH];   // (C0, C1, d, 0)   * 2log2e
__device__ float2 gF[NFC];   // fc1_w · sw  (natural scale)
__device__ float  gfb[NFC];  // fc1_w · sb + fc1_b

__device__ __forceinline__ float ex2_approx(float x) {
    float y; asm("ex2.approx.f32 %0, %1;" : "=f"(y) : "f"(x)); return y;
}
__device__ __forceinline__ float rcp_approx(float x) {
    float y; asm("rcp.approx.f32 %0, %1;" : "=f"(y) : "f"(x)); return y;
}

// ---------------------------------------------------------------------------
// Precompute kernel: fold W through the 1x1-conv encoders.
// Blocks 0..255: row h of A/B/C/d.  Blocks 256..275: row j of F/fb.
// 256 threads/block, one k per thread, coalesced reads of W rows.
// ---------------------------------------------------------------------------
__global__ void precompute_kernel(
    const float* __restrict__ sw, const float* __restrict__ sb,
    const float* __restrict__ dw, const float* __restrict__ db,
    const float* __restrict__ W,
    const float* __restrict__ fc1_w, const float* __restrict__ fc1_b)
{
    const float KS = 2.8853900817779268f;  // 2*log2(e)
    __shared__ float sred[8][8];
    int tid = threadIdx.x;
    int blk = blockIdx.x;
    int lane = tid & 31, w = tid >> 5;

    if (blk < NH) {
        int h = blk;
        float ws = W[h * K3 + tid];
        float wd = W[h * K3 + 256 + tid];
        float wc = W[h * K3 + 512 + tid];
        float s0 = sw[tid * 2 + 0], s1 = sw[tid * 2 + 1];
        float sbk = sb[tid];
        float p[7];
        p[0] = ws * s0;                          // A0
        p[1] = ws * s1;                          // A1
        p[2] = wd * dw[tid * 2 + 0];             // B0
        p[3] = wd * dw[tid * 2 + 1];             // B1
        p[4] = wc * s0;                          // C0
        p[5] = wc * s1;                          // C1
        p[6] = ws * sbk + wd * db[tid] + wc * sbk;  // d
        #pragma unroll
        for (int o = 16; o > 0; o >>= 1)
            #pragma unroll
            for (int i = 0; i < 7; i++)
                p[i] += __shfl_xor_sync(0xffffffffu, p[i], o);
        if (lane == 0) {
            #pragma unroll
            for (int i = 0; i < 7; i++) sred[w][i] = p[i];
        }
        __syncthreads();
        if (tid == 0) {
            float q[7];
            #pragma unroll
            for (int i = 0; i < 7; i++) {
                q[i] = 0.f;
                for (int ww = 0; ww < 8; ww++) q[i] += sred[ww][i];
            }
            gAB[h] = make_float4(q[0] * KS, q[1] * KS, q[2] * KS, q[3] * KS);
            gCd[h] = make_float4(q[4] * KS, q[5] * KS, q[6] * KS, 0.f);
        }
    } else {
        int j = blk - NH;  // 0..19
        float fw = fc1_w[j * NH + tid];
        float p0 = fw * sw[tid * 2 + 0];
        float p1 = fw * sw[tid * 2 + 1];
        float p2 = fw * sb[tid];
        #pragma unroll
        for (int o = 16; o > 0; o >>= 1) {
            p0 += __shfl_xor_sync(0xffffffffu, p0, o);
            p1 += __shfl_xor_sync(0xffffffffu, p1, o);
            p2 += __shfl_xor_sync(0xffffffffu, p2, o);
        }
        if (lane == 0) { sred[w][0] = p0; sred[w][1] = p1; sred[w][2] = p2; }
        __syncthreads();
        if (tid == 0) {
            float q0 = 0.f, q1 = 0.f, q2 = 0.f;
            for (int ww = 0; ww < 8; ww++) {
                q0 += sred[ww][0]; q1 += sred[ww][1]; q2 += sred[ww][2];
            }
            gF[j] = make_float2(q0, q1);
            gfb[j] = q2 + fc1_b[j];
        }
    }
}

// ---------------------------------------------------------------------------
// Main kernel: one block per batch element b, one thread per sequence pos s.
// All 3 attention iterations + softmax + context update + output MLP in-block.
// ---------------------------------------------------------------------------
__global__ void __launch_bounds__(1024)
attn_kernel(const float* __restrict__ stat, const float* __restrict__ dyn,
            const float* __restrict__ istate, const float* __restrict__ v,
            const float* __restrict__ fc2_w, const float* __restrict__ fc2_b,
            float* __restrict__ out)
{
    __shared__ float4 sAB[NH];
    __shared__ float2 svg[NH];      // (v[h], g[h]); g rewritten each iteration
    __shared__ float4 sCd[NH];
    __shared__ float sredM[32];
    __shared__ float sredP[32], sredX[32], sredY[32];
    __shared__ float bc[4];         // broadcast: [0]=max, [1]=sumP, [2]=sPx0, [3]=sPx1

    const float LOG2E = 1.4426950408889634f;
    int b = blockIdx.x;
    int s = threadIdx.x;
    int lane = s & 31, warp = s >> 5;

    float x0 = stat[b * 2 * NS + s];
    float x1 = stat[b * 2 * NS + NS + s];
    float y0 = dyn[b * 2 * NS + s];
    float y1 = dyn[b * 2 * NS + NS + s];

    if (s < NH) {
        sAB[s] = gAB[s];
        sCd[s] = gCd[s];
        svg[s].x = v[s];
    }

    float z0 = istate[b * 2 + 0];
    float z1 = istate[b * 2 + 1];

    for (int it = 0; it < NITER; it++) {
        __syncthreads();                 // prior reads of svg done; coeff loads visible
        if (s < NH) {
            float4 cd = sCd[s];
            svg[s].y = fmaf(cd.x, z0, fmaf(cd.y, z1, cd.z));
        }
        __syncthreads();

        // score t = sum_h v[h] * tanh(arg_h), arg already in exp2 domain
        float t = 0.f;
        #pragma unroll 4
        for (int h = 0; h < NH; h++) {
            float4 ab = sAB[h];
            float2 vg = svg[h];
            float arg = vg.y;
            arg = fmaf(ab.x, x0, arg);
            arg = fmaf(ab.y, x1, arg);
            arg = fmaf(ab.z, y0, arg);
            arg = fmaf(ab.w, y1, arg);
            float ex = ex2_approx(arg);
            float th = fmaf(-2.f, rcp_approx(ex + 1.f), 1.f);  // tanh, NaN-safe
            t = fmaf(vg.x, th, t);
        }

        // block max over S
        float m = t;
        #pragma unroll
        for (int o = 16; o > 0; o >>= 1)
            m = fmaxf(m, __shfl_xor_sync(0xffffffffu, m, o));
        if (lane == 0) sredM[warp] = m;
        __syncthreads();
        if (s < 32) {
            float mm = sredM[s];
            #pragma unroll
            for (int o = 16; o > 0; o >>= 1)
                mm = fmaxf(mm, __shfl_xor_sync(0xffffffffu, mm, o));
            if (s == 0) bc[0] = mm;
        }
        __syncthreads();
        float M = bc[0];

        // softmax weights + weighted feature sums
        float p = ex2_approx((t - M) * LOG2E);
        float a = p, bx = p * x0, by = p * x1;
        #pragma unroll
        for (int o = 16; o > 0; o >>= 1) {
            a  += __shfl_xor_sync(0xffffffffu, a,  o);
            bx += __shfl_xor_sync(0xffffffffu, bx, o);
            by += __shfl_xor_sync(0xffffffffu, by, o);
        }
        if (lane == 0) { sredP[warp] = a; sredX[warp] = bx; sredY[warp] = by; }
        __syncthreads();
        if (s < 32) {
            float aa = sredP[s], xx = sredX[s], yy = sredY[s];
            #pragma unroll
            for (int o = 16; o > 0; o >>= 1) {
                aa += __shfl_xor_sync(0xffffffffu, aa, o);
                xx += __shfl_xor_sync(0xffffffffu, xx, o);
                yy += __shfl_xor_sync(0xffffffffu, yy, o);
            }
            if (s == 0) { bc[1] = aa; bc[2] = xx; bc[3] = yy; }
        }
        __syncthreads();
        float inv = 1.f / bc[1];
        z0 = bc[2] * inv;                // xbar0
        z1 = bc[3] * inv;                // xbar1
    }

    // Output MLP (folded through sw): out[b] = fc2_b + fc2_w · relu(F·xbar + fb)
    if (s == 0) {
        float o = fc2_b[0];
        #pragma unroll
        for (int j = 0; j < NFC; j++) {
            float hv = fmaf(gF[j].x, z0, fmaf(gF[j].y, z1, gfb[j]));
            hv = fmaxf(hv, 0.f);
            o = fmaf(fc2_w[j], hv, o);
        }
        out[b] = o;
    }
}

extern "C" void kernel_launch(void* const* d_in, const int* in_sizes, int n_in,
                              void* d_out, int out_size)
{
    const float* stat   = (const float*)d_in[0];   // [256, 2, 1024]
    const float* dyn    = (const float*)d_in[1];   // [256, 2, 1024]
    const float* istate = (const float*)d_in[2];   // [256, 2]
    const float* sw     = (const float*)d_in[3];   // [256, 2]
    const float* sb     = (const float*)d_in[4];   // [256]
    const float* dw     = (const float*)d_in[5];   // [256, 2]
    const float* db     = (const float*)d_in[6];   // [256]
    const float* v      = (const float*)d_in[7];   // [1, 256]
    const float* W      = (const float*)d_in[8];   // [256, 768]
    const float* fc1_w  = (const float*)d_in[9];   // [20, 256]
    const float* fc1_b  = (const float*)d_in[10];  // [20]
    const float* fc2_w  = (const float*)d_in[11];  // [1, 20]
    const float* fc2_b  = (const float*)d_in[12];  // [1]
    float* out = (float*)d_out;                    // [256, 1]

    precompute_kernel<<<NH + NFC, 256>>>(sw, sb, dw, db, W, fc1_w, fc1_b);
    attn_kernel<<<NB, NS>>>(stat, dyn, istate, v, fc2_w, fc2_b, out);
}

// round 3
// speedup vs baseline: 1.8540x; 1.8540x over previous
#include <cuda_runtime.h>

// Critic_66511863546286 — folded attention critic, round 3.
// B=256, S=1024, H=256, feat dims = 2, 3 iterations.
// R3: tanh.approx.f32 (single MUFU per point instead of ex2+rcp chain),
// 2 sequence points per thread, compact coefficient layout.
// (f32x2 packed FMA dropped: MUFU binds, not issue — and it was the only
//  exotic-instruction risk after two bench-infra failures.)

#define NB 256
#define NS 1024
#define NH 256
#define K3 768
#define NITER 3
#define NFC 20
#define BT 512   // threads per block; thread t owns points t and t+512

// Precomputed fused coefficients (natural scale; tanh.approx takes raw arg).
__device__ float4 gAB[NH];   // (A0, A1, B0, B1)
__device__ float4 gCdv[NH];  // (C0, C1, d, v[h])
__device__ float2 gF[NFC];   // fc1_w · sw
__device__ float  gfb[NFC];  // fc1_w · sb + fc1_b

__device__ __forceinline__ float ex2_approx(float x) {
    float y; asm("ex2.approx.f32 %0, %1;" : "=f"(y) : "f"(x)); return y;
}
__device__ __forceinline__ float tanh_approx(float x) {
    float y; asm("tanh.approx.f32 %0, %1;" : "=f"(y) : "f"(x)); return y;
}

// ---------------------------------------------------------------------------
// Precompute: fold W through the 1x1-conv encoders.
// Blocks 0..255 -> row h of A/B/C/d (+v).  Blocks 256..275 -> row j of F/fb.
// ---------------------------------------------------------------------------
__global__ void precompute_kernel(
    const float* __restrict__ sw, const float* __restrict__ sb,
    const float* __restrict__ dw, const float* __restrict__ db,
    const float* __restrict__ W,  const float* __restrict__ v,
    const float* __restrict__ fc1_w, const float* __restrict__ fc1_b)
{
    __shared__ float sred[8][8];
    int tid = threadIdx.x;
    int blk = blockIdx.x;
    int lane = tid & 31, w = tid >> 5;

    if (blk < NH) {
        int h = blk;
        float ws = W[h * K3 + tid];
        float wd = W[h * K3 + 256 + tid];
        float wc = W[h * K3 + 512 + tid];
        float s0 = sw[tid * 2 + 0], s1 = sw[tid * 2 + 1];
        float sbk = sb[tid];
        float p[7];
        p[0] = ws * s0;                             // A0
        p[1] = ws * s1;                             // A1
        p[2] = wd * dw[tid * 2 + 0];                // B0
        p[3] = wd * dw[tid * 2 + 1];                // B1
        p[4] = wc * s0;                             // C0
        p[5] = wc * s1;                             // C1
        p[6] = ws * sbk + wd * db[tid] + wc * sbk;  // d
        #pragma unroll
        for (int o = 16; o > 0; o >>= 1)
            #pragma unroll
            for (int i = 0; i < 7; i++)
                p[i] += __shfl_xor_sync(0xffffffffu, p[i], o);
        if (lane == 0) {
            #pragma unroll
            for (int i = 0; i < 7; i++) sred[w][i] = p[i];
        }
        __syncthreads();
        if (tid == 0) {
            float q[7];
            #pragma unroll
            for (int i = 0; i < 7; i++) {
                q[i] = 0.f;
                for (int ww = 0; ww < 8; ww++) q[i] += sred[ww][i];
            }
            gAB[h]  = make_float4(q[0], q[1], q[2], q[3]);
            gCdv[h] = make_float4(q[4], q[5], q[6], v[h]);
        }
    } else {
        int j = blk - NH;  // 0..19
        float fw = fc1_w[j * NH + tid];
        float p0 = fw * sw[tid * 2 + 0];
        float p1 = fw * sw[tid * 2 + 1];
        float p2 = fw * sb[tid];
        #pragma unroll
        for (int o = 16; o > 0; o >>= 1) {
            p0 += __shfl_xor_sync(0xffffffffu, p0, o);
            p1 += __shfl_xor_sync(0xffffffffu, p1, o);
            p2 += __shfl_xor_sync(0xffffffffu, p2, o);
        }
        if (lane == 0) { sred[w][0] = p0; sred[w][1] = p1; sred[w][2] = p2; }
        __syncthreads();
        if (tid == 0) {
            float q0 = 0.f, q1 = 0.f, q2 = 0.f;
            for (int ww = 0; ww < 8; ww++) {
                q0 += sred[ww][0]; q1 += sred[ww][1]; q2 += sred[ww][2];
            }
            gF[j] = make_float2(q0, q1);
            gfb[j] = q2 + fc1_b[j];
        }
    }
}

// ---------------------------------------------------------------------------
// Main kernel: one block per batch element; 512 threads; thread t owns
// sequence points t (lo) and t+512 (hi).
// ---------------------------------------------------------------------------
__global__ void __launch_bounds__(BT)
attn_kernel(const float* __restrict__ stat, const float* __restrict__ dyn,
            const float* __restrict__ istate,
            const float* __restrict__ fc2_w, const float* __restrict__ fc2_b,
            float* __restrict__ out)
{
    __shared__ float4 sAB[NH];     // (A0,A1,B0,B1)
    __shared__ float4 sCdv[NH];    // (C0,C1,d,v)
    __shared__ float2 sGV[NH];     // (g, v) rewritten each iteration
    __shared__ float sredM[16], sredP[16], sredX[16], sredY[16];
    __shared__ float bc[4];        // [0]=max [1]=sumP [2]=sum p*x0 [3]=sum p*x1

    const float LOG2E = 1.4426950408889634f;
    int b = blockIdx.x;
    int s = threadIdx.x;           // 0..511
    int lane = s & 31, warp = s >> 5;

    // features for points s (lo) and s+512 (hi)
    float x0l = stat[b * 2 * NS + s],        x0h = stat[b * 2 * NS + s + BT];
    float x1l = stat[b * 2 * NS + NS + s],   x1h = stat[b * 2 * NS + NS + s + BT];
    float y0l = dyn[b * 2 * NS + s],         y0h = dyn[b * 2 * NS + s + BT];
    float y1l = dyn[b * 2 * NS + NS + s],    y1h = dyn[b * 2 * NS + NS + s + BT];

    if (s < NH) {
        sAB[s] = gAB[s];
        sCdv[s] = gCdv[s];
    }

    float z0 = istate[b * 2 + 0];
    float z1 = istate[b * 2 + 1];

    for (int it = 0; it < NITER; it++) {
        __syncthreads();
        if (s < NH) {
            float4 cd = sCdv[s];
            float g = fmaf(cd.x, z0, fmaf(cd.y, z1, cd.z));
            sGV[s] = make_float2(g, cd.w);
        }
        __syncthreads();

        // scores for both points: t = sum_h v[h] * tanh(A·x + B·y + g)
        float t0 = 0.f, t1 = 0.f;
        #pragma unroll 4
        for (int h = 0; h < NH; h++) {
            float4 ab = sAB[h];
            float2 gv = sGV[h];
            float al = gv.x, ah = gv.x;
            al = fmaf(ab.x, x0l, al);   ah = fmaf(ab.x, x0h, ah);
            al = fmaf(ab.y, x1l, al);   ah = fmaf(ab.y, x1h, ah);
            al = fmaf(ab.z, y0l, al);   ah = fmaf(ab.z, y0h, ah);
            al = fmaf(ab.w, y1l, al);   ah = fmaf(ab.w, y1h, ah);
            t0 = fmaf(gv.y, tanh_approx(al), t0);
            t1 = fmaf(gv.y, tanh_approx(ah), t1);
        }

        // block max over all 1024 points
        float m = fmaxf(t0, t1);
        #pragma unroll
        for (int o = 16; o > 0; o >>= 1)
            m = fmaxf(m, __shfl_xor_sync(0xffffffffu, m, o));
        if (lane == 0) sredM[warp] = m;
        __syncthreads();
        if (s < 16) {
            float mm = sredM[s];
            #pragma unroll
            for (int o = 8; o > 0; o >>= 1)
                mm = fmaxf(mm, __shfl_xor_sync(0xffffu, mm, o));
            if (s == 0) bc[0] = mm;
        }
        __syncthreads();
        float M = bc[0];

        // softmax weights + weighted feature sums
        float p0 = ex2_approx((t0 - M) * LOG2E);
        float p1 = ex2_approx((t1 - M) * LOG2E);
        float a  = p0 + p1;
        float bx = fmaf(p0, x0l, p1 * x0h);
        float by = fmaf(p0, x1l, p1 * x1h);
        #pragma unroll
        for (int o = 16; o > 0; o >>= 1) {
            a  += __shfl_xor_sync(0xffffffffu, a,  o);
            bx += __shfl_xor_sync(0xffffffffu, bx, o);
            by += __shfl_xor_sync(0xffffffffu, by, o);
        }
        if (lane == 0) { sredP[warp] = a; sredX[warp] = bx; sredY[warp] = by; }
        __syncthreads();
        if (s < 16) {
            float aa = sredP[s], xx = sredX[s], yy = sredY[s];
            #pragma unroll
            for (int o = 8; o > 0; o >>= 1) {
                aa += __shfl_xor_sync(0xffffu, aa, o);
                xx += __shfl_xor_sync(0xffffu, xx, o);
                yy += __shfl_xor_sync(0xffffu, yy, o);
            }
            if (s == 0) { bc[1] = aa; bc[2] = xx; bc[3] = yy; }
        }
        __syncthreads();
        float inv = 1.f / bc[1];
        z0 = bc[2] * inv;   // xbar0
        z1 = bc[3] * inv;   // xbar1
    }

    // Output MLP (folded through sw)
    if (s == 0) {
        float o = fc2_b[0];
        #pragma unroll
        for (int j = 0; j < NFC; j++) {
            float hv = fmaf(gF[j].x, z0, fmaf(gF[j].y, z1, gfb[j]));
            hv = fmaxf(hv, 0.f);
            o = fmaf(fc2_w[j], hv, o);
        }
        out[b] = o;
    }
}

extern "C" void kernel_launch(void* const* d_in, const int* in_sizes, int n_in,
                              void* d_out, int out_size)
{
    const float* stat   = (const float*)d_in[0];   // [256, 2, 1024]
    const float* dyn    = (const float*)d_in[1];   // [256, 2, 1024]
    const float* istate = (const float*)d_in[2];   // [256, 2]
    const float* sw     = (const float*)d_in[3];   // [256, 2]
    const float* sb     = (const float*)d_in[4];   // [256]
    const float* dw     = (const float*)d_in[5];   // [256, 2]
    const float* db     = (const float*)d_in[6];   // [256]
    const float* v      = (const float*)d_in[7];   // [1, 256]
    const float* W      = (const float*)d_in[8];   // [256, 768]
    const float* fc1_w  = (const float*)d_in[9];   // [20, 256]
    const float* fc1_b  = (const float*)d_in[10];  // [20]
    const float* fc2_w  = (const float*)d_in[11];  // [1, 20]
    const float* fc2_b  = (const float*)d_in[12];  // [1]
    float* out = (float*)d_out;                    // [256, 1]

    precompute_kernel<<<NH + NFC, 256>>>(sw, sb, dw, db, W, v, fc1_w, fc1_b);
    attn_kernel<<<NB, BT>>>(stat, dyn, istate, fc2_w, fc2_b, out);
}